// round 5
// baseline (speedup 1.0000x reference)
#include <cuda_runtime.h>

#define Nn   128
#define Hh   2
#define Ll   1024
#define Cc   (Hh * Ll)      /* 2048 columns = h*L flattened */
#define PRED (Nn * Cc)      /* 262144 */

#define SB_LD  64           /* [m][c] alpha tile: 128 x 64, no pad needed */
#define SA2_LD 128          /* [k][m] packed splat Amat tile: 16 x 128 */

__device__ float g_alpha[PRED];
__device__ float g_Ss[PRED];

// ---- packed fp32x2 helpers (sm_103a FFMA2 path, PTX-only) ------------------
__device__ __forceinline__ unsigned long long pack2(float lo, float hi) {
    unsigned long long r;
    asm("mov.b64 %0, {%1, %2};" : "=l"(r) : "f"(lo), "f"(hi));
    return r;
}
__device__ __forceinline__ void unpack2(unsigned long long v, float& lo, float& hi) {
    asm("mov.b64 {%0, %1}, %2;" : "=f"(lo), "=f"(hi) : "l"(v));
}
__device__ __forceinline__ unsigned long long ffma2(unsigned long long a,
                                                    unsigned long long b,
                                                    unsigned long long c) {
    unsigned long long d;
    asm("fma.rn.f32x2 %0, %1, %2, %3;" : "=l"(d) : "l"(a), "l"(b), "l"(c));
    return d;
}

// ---------------------------------------------------------------------------
// Kernel 1: per-(n,h)-row fused relu + cumsum + exponential-decay recurrence.
// Also emits the third output (Amat + I), which needs no scan data.
// ---------------------------------------------------------------------------
__global__ void __launch_bounds__(128) scan_kernel(const float* __restrict__ x,
                                                   const float* __restrict__ Amat,
                                                   const float* __restrict__ taus,
                                                   const float* __restrict__ r0dt,
                                                   float* __restrict__ out)
{
    int row  = blockIdx.x;          // n*H + h
    int t    = threadIdx.x;         // 0..127
    int lane = t & 31, wid = t >> 5;
    int base = row * Ll + t * 8;

    const float4* xv = reinterpret_cast<const float4*>(x + base);
    float4 v0 = xv[0], v1 = xv[1];
    float s[8] = { fmaxf(v0.x, 0.f), fmaxf(v0.y, 0.f), fmaxf(v0.z, 0.f), fmaxf(v0.w, 0.f),
                   fmaxf(v1.x, 0.f), fmaxf(v1.y, 0.f), fmaxf(v1.z, 0.f), fmaxf(v1.w, 0.f) };

    // third output: tempAmat.T = Amat + I  (first 128 blocks each do one row)
    if (row < 128) {
        int idx = row * 128 + t;
        out[2 * PRED + idx] = Amat[idx] + (row == t ? 1.f : 0.f);
    }

    float tau = taus[row];
    float R0  = r0dt[row];
    float d   = 1.f - 1.f / tau;

    float cum = 0.f, isv = 0.f;
#pragma unroll
    for (int k = 0; k < 8; k++) { cum += s[k]; isv = fmaf(d, isv, s[k]); }

    float d2 = d * d, d4 = d2 * d2, r8 = d4 * d4;   // d^8

    float inclI = isv, inclC = cum, rp = r8;
#pragma unroll
    for (int off = 1; off < 32; off <<= 1) {
        float ui = __shfl_up_sync(0xffffffffu, inclI, off);
        float uc = __shfl_up_sync(0xffffffffu, inclC, off);
        if (lane >= off) { inclI = fmaf(rp, ui, inclI); inclC += uc; }
        rp *= rp;
    }

    __shared__ float wI[4], wC[4];
    if (lane == 31) { wI[wid] = inclI; wC[wid] = inclC; }
    __syncthreads();

    float Rw = rp;                                  // d^256
    float exI = 0.f, exC = 0.f, aI = 0.f, aC = 0.f;
#pragma unroll
    for (int w = 0; w < 4; w++) {
        if (w == wid) { exI = aI; exC = aC; }
        aI = fmaf(Rw, aI, wI[w]);
        aC += wC[w];
    }

    float upI = __shfl_up_sync(0xffffffffu, inclI, 1);
    float upC = __shfl_up_sync(0xffffffffu, inclC, 1);
    if (lane == 0) { upI = 0.f; upC = 0.f; }
    float XI = fmaf(exI, __powf(r8, (float)lane), upI);
    float XC = upC + exC;

    float al[8], ss[8];
    float ci = XI, cc = XC;
#pragma unroll
    for (int k = 0; k < 8; k++) {
        ci = fmaf(d, ci, s[k]);
        cc += s[k];
        al[k] = 1.f - __expf(-R0 * ci);
        ss[k] = 1.f - cc;
    }

    float4* ga = reinterpret_cast<float4*>(g_alpha + base);
    ga[0] = make_float4(al[0], al[1], al[2], al[3]);
    ga[1] = make_float4(al[4], al[5], al[6], al[7]);
    float4* gs = reinterpret_cast<float4*>(g_Ss + base);
    gs[0] = make_float4(ss[0], ss[1], ss[2], ss[3]);
    gs[1] = make_float4(ss[4], ss[5], ss[6], ss[7]);
    float4* go = reinterpret_cast<float4*>(out + PRED + base);   // signal output
    go[0] = make_float4(s[0], s[1], s[2], s[3]);
    go[1] = make_float4(s[4], s[5], s[6], s[7]);
}

// ---------------------------------------------------------------------------
// Kernel 2: Alpha = alpha + Amat @ alpha ;  pred = Alpha * Ss.
// Grid (32 col-tiles x 8 row-tiles) = 256 blocks; 256 threads; block tile
// 16 rows x 64 cols; thread tile 1 row x 4 cols as 2 packed f32x2 accs.
// Amat tile stored PRE-SPLATTED ((a,a) pairs): mainloop per m is
// LDS.64 + LDS.128 + 2 FFMA2.
// ---------------------------------------------------------------------------
__global__ void __launch_bounds__(256, 2) gemm_kernel(const float* __restrict__ Amat,
                                                      float* __restrict__ out)
{
    __shared__ float sB[128 * SB_LD];                      // 32 KB
    __shared__ unsigned long long sA2[16 * SA2_LD];        // 16 KB (splatted)

    int bx = blockIdx.x;               // 64-col tile (0..31)
    int by = blockIdx.y;               // 16-row tile (0..7)
    int tid = threadIdx.x;
    int k0 = by * 16, c0 = bx * 64;

    // fill sA2[k][m] = (Amat[k0+k][m], Amat[k0+k][m]) — coalesced over m
#pragma unroll
    for (int j = 0; j < 8; j++) {
        int i = j * 256 + tid;
        int k = i >> 7, m = i & 127;
        float a = Amat[(k0 + k) * 128 + m];
        sA2[k * SA2_LD + m] = pack2(a, a);
    }
    // fill sB: 2048 float4 quads / 256 threads = 8 iters
#pragma unroll
    for (int j = 0; j < 8; j++) {
        int i = j * 256 + tid;
        int m = i >> 4, cq = i & 15;
        float4 v = *reinterpret_cast<const float4*>(&g_alpha[m * Cc + c0 + cq * 4]);
        *reinterpret_cast<float4*>(&sB[m * SB_LD + cq * 4]) = v;
    }
    __syncthreads();

    int tx = tid & 15;                 // col quad: local cols 4*tx .. +3
    int ty = tid >> 4;                 // local row 0..15
    int cl = 4 * tx;

    // identity seed: Alpha = alpha + Amat@alpha  (row k0+ty lives in sB)
    float4 iv = *reinterpret_cast<float4*>(&sB[(k0 + ty) * SB_LD + cl]);
    unsigned long long acc0 = pack2(iv.x, iv.y);
    unsigned long long acc1 = pack2(iv.z, iv.w);

    const unsigned long long* aRow = &sA2[ty * SA2_LD];

#pragma unroll 16
    for (int m = 0; m < 128; m++) {
        float4 bv = *reinterpret_cast<float4*>(&sB[m * SB_LD + cl]);
        unsigned long long ap = aRow[m];
        acc0 = ffma2(ap, pack2(bv.x, bv.y), acc0);
        acc1 = ffma2(ap, pack2(bv.z, bv.w), acc1);
    }

    int gk = k0 + ty;
    const float4 ssv = *reinterpret_cast<const float4*>(&g_Ss[gk * Cc + c0 + cl]);
    float r0, r1, r2, r3;
    unpack2(acc0, r0, r1);
    unpack2(acc1, r2, r3);
    float4 o = make_float4(r0 * ssv.x, r1 * ssv.y, r2 * ssv.z, r3 * ssv.w);
    *reinterpret_cast<float4*>(&out[gk * Cc + c0 + cl]) = o;
}

extern "C" void kernel_launch(void* const* d_in, const int* in_sizes, int n_in,
                              void* d_out, int out_size)
{
    const float* x    = (const float*)d_in[0];
    const float* Amat = (const float*)d_in[1];
    const float* taus = (const float*)d_in[2];
    const float* r0   = (const float*)d_in[3];
    float* out = (float*)d_out;

    (void)in_sizes; (void)n_in; (void)out_size;

    scan_kernel<<<Nn * Hh, 128>>>(x, Amat, taus, r0, out);
    gemm_kernel<<<dim3(32, 8), 256>>>(Amat, out);
}